// round 7
// baseline (speedup 1.0000x reference)
#include <cuda_runtime.h>
#include <cuda_fp16.h>
#include <cstdint>
#include <float.h>

#define NPIX 65536
#define FDIM 224
#define PDIM 6
#define HDIM 256
#define NCHUNK 512          // pixel chunks for endmember/yhat (128 px each)

// ------------------------- static device scratch ---------------------------
__device__ __half g_Yh[NPIX * FDIM];
__device__ __half g_Yl[NPIX * FDIM];
__device__ __half g_h1h[NPIX * HDIM];
__device__ __half g_h1l[NPIX * HDIM];
__device__ __half g_h2h[NPIX * HDIM];
__device__ __half g_h2l[NPIX * HDIM];
__device__ float  g_logits[NPIX * FDIM];
__device__ int    g_cls[NPIX];
__device__ float  g_M[PDIM * FDIM];
__device__ __half g_W1Th[HDIM * FDIM];
__device__ __half g_W1Tl[HDIM * FDIM];
__device__ __half g_W2Th[HDIM * HDIM];
__device__ __half g_W2Tl[HDIM * HDIM];
__device__ __half g_W3Th[FDIM * HDIM];
__device__ __half g_W3Tl[FDIM * HDIM];
__device__ float  g_part[NCHUNK * PDIM * 3 * FDIM];

// ------------------------------ PTX helpers --------------------------------
__device__ __forceinline__ uint32_t smem_u32(const void* p) {
    uint32_t a;
    asm("{ .reg .u64 t; cvta.to.shared.u64 t, %1; cvt.u32.u64 %0, t; }"
        : "=r"(a) : "l"(p));
    return a;
}
__device__ __forceinline__ void cpa16(uint32_t dst, const void* src, uint32_t sz) {
    asm volatile("cp.async.cg.shared.global [%0], [%1], 16, %2;"
                 :: "r"(dst), "l"(src), "r"(sz) : "memory");
}
__device__ __forceinline__ void cpa_commit() {
    asm volatile("cp.async.commit_group;" ::: "memory");
}
template <int n> __device__ __forceinline__ void cpa_wait() {
    asm volatile("cp.async.wait_group %0;" :: "n"(n) : "memory");
}
__device__ __forceinline__ void ldsm4(uint32_t* r, uint32_t addr) {
    asm volatile("ldmatrix.sync.aligned.m8n8.x4.shared.b16 {%0,%1,%2,%3}, [%4];"
                 : "=r"(r[0]), "=r"(r[1]), "=r"(r[2]), "=r"(r[3]) : "r"(addr));
}
__device__ __forceinline__ void mma_f16(float* d, const uint32_t* a, const uint32_t* b) {
    asm volatile(
        "mma.sync.aligned.m16n8k16.row.col.f32.f16.f16.f32 "
        "{%0,%1,%2,%3}, {%4,%5,%6,%7}, {%8,%9}, {%0,%1,%2,%3};"
        : "+f"(d[0]), "+f"(d[1]), "+f"(d[2]), "+f"(d[3])
        : "r"(a[0]), "r"(a[1]), "r"(a[2]), "r"(a[3]), "r"(b[0]), "r"(b[1]));
}
__device__ __forceinline__ void split_h(float v, __half& hi, __half& lo) {
    hi = __float2half_rn(v);
    lo = __float2half_rn(v - __half2float(hi));
}

// ---------------------------------------------------------------------------
// fp16x3 mma.sync GEMM: C = act(A @ BT^T + bias), fp32-accurate.
// Operands pre-split: A = Ah + Al, BT = Bh + Bl (all __half, K-contiguous).
// Block tile 128x64, 8 warps (4x2), warp tile 32x32, K chunks 32, cp.async x2.
// 3 CTAs/SM (24 warps) for latency hiding on the tensor pipe.
// ---------------------------------------------------------------------------
template <int N, int K, bool RELU, bool SPLIT_OUT>
__global__ __launch_bounds__(256, 3) void mma_gemm_f16(
    const __half* __restrict__ Ah, const __half* __restrict__ Al,
    const __half* __restrict__ Bh, const __half* __restrict__ Bl,
    const float* __restrict__ bias,
    float* __restrict__ Cf, __half* __restrict__ Ch, __half* __restrict__ Cl)
{
    constexpr int NC = K / 32;
    constexpr int ROWB = 80;                 // bytes per smem row (64B data + pad)
    constexpr int ACOMP = 128 * ROWB;        // 10240
    constexpr int BCOMP = 64 * ROWB;         // 5120
    constexpr int STAGEB = 2 * ACOMP + 2 * BCOMP;  // 30720: [Ah][Al][Bh][Bl]

    extern __shared__ char sh[];
    const uint32_t sb = smem_u32(sh);

    const int t = threadIdx.x;
    const int lane = t & 31, wid = t >> 5;
    const int wr = wid >> 1;                 // 0..3 (m)
    const int wc = wid & 1;                  // 0..1 (n)
    const int row0 = blockIdx.y * 128;
    const int col0 = blockIdx.x * 64;

    float acc[2][4][4];
#pragma unroll
    for (int i = 0; i < 2; i++)
#pragma unroll
        for (int j = 0; j < 4; j++)
#pragma unroll
            for (int k = 0; k < 4; k++) acc[i][j][k] = 0.0f;

    // ---- cp.async mapping: thread t -> row cr (0..63), 16B group g ----
    const int cr = t >> 2;
    const int g  = t & 3;
    const uint32_t dOff1 = (uint32_t)(cr * ROWB + g * 16);
    const uint32_t dOff2 = dOff1 + (uint32_t)(64 * ROWB);

    const __half* Ah0 = Ah + (long)(row0 + cr) * K + g * 8;
    const __half* Al0 = Al + (long)(row0 + cr) * K + g * 8;
    int bn = col0 + cr;
    const uint32_t bs = (bn < N) ? 16u : 0u;
    if (bn >= N) bn = N - 1;
    const __half* Bh0 = Bh + (long)bn * K + g * 8;
    const __half* Bl0 = Bl + (long)bn * K + g * 8;

    // ---- ldmatrix lane offsets ----
    const uint32_t aLm = (uint32_t)((wr * 32 + (lane & 15)) * ROWB + (lane >> 4) * 16);
    const uint32_t bLm = (uint32_t)((wc * 32 + (lane & 7) + ((lane >> 4) << 3)) * ROWB
                                    + ((lane >> 3) & 1) * 16);

    auto load_chunk = [&](int stage, int k0) {
        const uint32_t st = sb + (uint32_t)(stage * STAGEB);
        cpa16(st + dOff1,                     Ah0 + k0,           16u);
        cpa16(st + dOff2,                     Ah0 + k0 + 64L * K, 16u);
        cpa16(st + ACOMP + dOff1,             Al0 + k0,           16u);
        cpa16(st + ACOMP + dOff2,             Al0 + k0 + 64L * K, 16u);
        cpa16(st + 2 * ACOMP + dOff1,         Bh0 + k0,           bs);
        cpa16(st + 2 * ACOMP + BCOMP + dOff1, Bl0 + k0,           bs);
        cpa_commit();
    };

    load_chunk(0, 0);

    for (int c = 0; c < NC; c++) {
        const int buf = c & 1;
        if (c + 1 < NC) {
            load_chunk(buf ^ 1, (c + 1) * 32);
            cpa_wait<1>();
        } else {
            cpa_wait<0>();
        }
        __syncthreads();

        const uint32_t st = sb + (uint32_t)(buf * STAGEB);
        const uint32_t aHB = st + aLm;
        const uint32_t aLB = st + ACOMP + aLm;
        const uint32_t bHB = st + 2 * ACOMP + bLm;
        const uint32_t bLB = st + 2 * ACOMP + BCOMP + bLm;

#pragma unroll
        for (int kk = 0; kk < 2; kk++) {
            uint32_t bh[4][2], bl[4][2];
#pragma unroll
            for (int pr = 0; pr < 2; pr++) {
                const uint32_t o = (uint32_t)(pr * 16 * ROWB + kk * 32);
                uint32_t r4[4];
                ldsm4(r4, bHB + o);
                bh[pr * 2][0] = r4[0]; bh[pr * 2][1] = r4[1];
                bh[pr * 2 + 1][0] = r4[2]; bh[pr * 2 + 1][1] = r4[3];
                ldsm4(r4, bLB + o);
                bl[pr * 2][0] = r4[0]; bl[pr * 2][1] = r4[1];
                bl[pr * 2 + 1][0] = r4[2]; bl[pr * 2 + 1][1] = r4[3];
            }
#pragma unroll
            for (int mt = 0; mt < 2; mt++) {
                const uint32_t o = (uint32_t)(mt * 16 * ROWB + kk * 32);
                uint32_t ah[4], al[4];
                ldsm4(ah, aHB + o);
                ldsm4(al, aLB + o);
#pragma unroll
                for (int nt = 0; nt < 4; nt++) mma_f16(acc[mt][nt], ah, bh[nt]);
#pragma unroll
                for (int nt = 0; nt < 4; nt++) mma_f16(acc[mt][nt], al, bh[nt]);
#pragma unroll
                for (int nt = 0; nt < 4; nt++) mma_f16(acc[mt][nt], ah, bl[nt]);
            }
        }
        __syncthreads();
    }

    // ---- epilogue ----
    const int rbase = row0 + wr * 32 + (lane >> 2);
    const int cbase = col0 + wc * 32 + (lane & 3) * 2;
#pragma unroll
    for (int nt = 0; nt < 4; nt++) {
        const int cc = cbase + nt * 8;
        if (cc < N) {
            const float bx = bias[cc], by = bias[cc + 1];
#pragma unroll
            for (int mt = 0; mt < 2; mt++) {
                const int r = rbase + mt * 16;
                float v[4];
                v[0] = acc[mt][nt][0] + bx; v[1] = acc[mt][nt][1] + by;
                v[2] = acc[mt][nt][2] + bx; v[3] = acc[mt][nt][3] + by;
                if (RELU) {
#pragma unroll
                    for (int q = 0; q < 4; q++) v[q] = fmaxf(v[q], 0.f);
                }
                if (SPLIT_OUT) {
                    __half h0, l0, h1x, l1, h2x, l2, h3, l3;
                    split_h(v[0], h0, l0); split_h(v[1], h1x, l1);
                    split_h(v[2], h2x, l2); split_h(v[3], h3, l3);
                    *(__half2*)&Ch[(long)r * N + cc]       = __halves2half2(h0, h1x);
                    *(__half2*)&Cl[(long)r * N + cc]       = __halves2half2(l0, l1);
                    *(__half2*)&Ch[(long)(r + 8) * N + cc] = __halves2half2(h2x, h3);
                    *(__half2*)&Cl[(long)(r + 8) * N + cc] = __halves2half2(l2, l3);
                } else {
                    *(float2*)&Cf[(long)r * N + cc]       = make_float2(v[0], v[1]);
                    *(float2*)&Cf[(long)(r + 8) * N + cc] = make_float2(v[2], v[3]);
                }
            }
        }
    }
}

// ---------------------------------------------------------------------------
// Split fp32 array -> (hi, lo) fp16 arrays. n multiple of 4.
// ---------------------------------------------------------------------------
__global__ __launch_bounds__(256) void split_kernel(
    const float* __restrict__ in, __half* __restrict__ hi, __half* __restrict__ lo,
    int n4)
{
    int i = blockIdx.x * 256 + threadIdx.x;
    if (i >= n4) return;
    float4 v = ((const float4*)in)[i];
    __half h0, l0, h1, l1, h2, l2, h3, l3;
    split_h(v.x, h0, l0); split_h(v.y, h1, l1);
    split_h(v.z, h2, l2); split_h(v.w, h3, l3);
    ((__half2*)hi)[i * 2]     = __halves2half2(h0, h1);
    ((__half2*)hi)[i * 2 + 1] = __halves2half2(h2, h3);
    ((__half2*)lo)[i * 2]     = __halves2half2(l0, l1);
    ((__half2*)lo)[i * 2 + 1] = __halves2half2(l2, l3);
}

// ---------------------------------------------------------------------------
// Fused transpose+split for all 3 weight matrices. grid (8,8,3), block (32,8).
// ---------------------------------------------------------------------------
__global__ void transpose_split_all(
    const float* __restrict__ W1, __half* __restrict__ T1h, __half* __restrict__ T1l,
    const float* __restrict__ W2, __half* __restrict__ T2h, __half* __restrict__ T2l,
    const float* __restrict__ W3, __half* __restrict__ T3h, __half* __restrict__ T3l)
{
    const float* W; __half* Th; __half* Tl; int R, C;
    if (blockIdx.z == 0)      { W = W1; Th = T1h; Tl = T1l; R = FDIM; C = HDIM; }
    else if (blockIdx.z == 1) { W = W2; Th = T2h; Tl = T2l; R = HDIM; C = HDIM; }
    else                      { W = W3; Th = T3h; Tl = T3l; R = HDIM; C = FDIM; }
    if ((int)blockIdx.x * 32 >= C || (int)blockIdx.y * 32 >= R) return;

    __shared__ float tb[32][33];
    int c = blockIdx.x * 32 + threadIdx.x;
    int r0 = blockIdx.y * 32;
    for (int j = threadIdx.y; j < 32; j += 8)
        tb[j][threadIdx.x] = W[(r0 + j) * C + c];
    __syncthreads();
    int rOut = r0 + threadIdx.x;
    int cBase = blockIdx.x * 32;
    for (int j = threadIdx.y; j < 32; j += 8) {
        float v = tb[threadIdx.x][j];
        __half h, l;
        split_h(v, h, l);
        Th[(long)(cBase + j) * R + rOut] = h;
        Tl[(long)(cBase + j) * R + rOut] = l;
    }
}

// ---------------------------------------------------------------------------
// argmax over P=6 per pixel, pixel-pair vectorized (12 floats = 3 float4).
// ---------------------------------------------------------------------------
__global__ __launch_bounds__(256) void cls_kernel2(
    const float* __restrict__ ab, int* __restrict__ cls)
{
    int i = blockIdx.x * 256 + threadIdx.x;   // pair index
    if (i >= NPIX / 2) return;
    const float4* p = (const float4*)(ab + (long)i * 12);
    float4 v0 = p[0], v1 = p[1], v2 = p[2];
    float a[6] = { v0.x, v0.y, v0.z, v0.w, v1.x, v1.y };
    float b[6] = { v1.z, v1.w, v2.x, v2.y, v2.z, v2.w };
    int ba = 0, bb = 0;
    float ma = a[0], mb = b[0];
#pragma unroll
    for (int q = 1; q < 6; q++) {
        if (a[q] > ma) { ma = a[q]; ba = q; }
        if (b[q] > mb) { mb = b[q]; bb = q; }
    }
    cls[i * 2] = ba;
    cls[i * 2 + 1] = bb;
}

// ---------------------------------------------------------------------------
// Endmember partials: thread <-> feature mapping, fully coalesced rows.
// grid NCHUNK blocks x 224 threads; each block: 128 consecutive pixels.
// ---------------------------------------------------------------------------
__global__ __launch_bounds__(224) void endmember_part2(
    const float* __restrict__ logits, const float* __restrict__ Y,
    const int* __restrict__ cls)
{
    const int blk = blockIdx.x;
    const int t = threadIdx.x;              // feature
    const int n0 = blk * (NPIX / NCHUNK);   // 128 pixels per chunk

    __shared__ int scls[NPIX / NCHUNK];
    for (int i = t; i < NPIX / NCHUNK; i += 224) scls[i] = cls[n0 + i];
    __syncthreads();

    float m[PDIM], s[PDIM], sy[PDIM];
#pragma unroll
    for (int p = 0; p < PDIM; p++) { m[p] = -FLT_MAX; s[p] = 0.f; sy[p] = 0.f; }

    for (int i = 0; i < NPIX / NCHUNK; i++) {
        const int c = scls[i];
        const long off = (long)(n0 + i) * FDIM + t;
        const float l = logits[off];
        const float y = Y[off];
        float mc = m[0], sc = s[0], syc = sy[0];
#pragma unroll
        for (int p = 1; p < PDIM; p++) {
            bool e = (c == p);
            mc = e ? m[p] : mc; sc = e ? s[p] : sc; syc = e ? sy[p] : syc;
        }
        float mn  = fmaxf(mc, l);
        float sca = __expf(mc - mn);
        float ea  = __expf(l - mn);
        float sn  = sc * sca + ea;
        float syn = syc * sca + ea * y;
#pragma unroll
        for (int p = 0; p < PDIM; p++) {
            bool e = (c == p);
            m[p] = e ? mn : m[p]; s[p] = e ? sn : s[p]; sy[p] = e ? syn : sy[p];
        }
    }

#pragma unroll
    for (int p = 0; p < PDIM; p++) {
        long base = (((long)blk * PDIM + p) * 3) * FDIM + t;
        g_part[base]             = m[p];
        g_part[base + FDIM]      = s[p];
        g_part[base + 2 * FDIM]  = sy[p];
    }
}

// grid PDIM blocks x 224 threads
__global__ __launch_bounds__(224) void endmember_combine2(float* __restrict__ Mo) {
    const int p = blockIdx.x;
    const int f = threadIdx.x;
    float m = -FLT_MAX, s = 0.f, sy = 0.f;
    for (int b = 0; b < NCHUNK; b++) {
        long base = (((long)b * PDIM + p) * 3) * FDIM + f;
        float m2 = g_part[base];
        float s2 = g_part[base + FDIM];
        float sy2 = g_part[base + 2 * FDIM];
        float mx = fmaxf(m, m2);
        float e1 = __expf(m - mx), e2 = __expf(m2 - mx);
        s  = s * e1 + s2 * e2;
        sy = sy * e1 + sy2 * e2;
        m = mx;
    }
    Mo[p * FDIM + f] = (s > 0.f) ? (sy / s) : 0.0f;
}

// ---------------------------------------------------------------------------
// Y_hat: grid NCHUNK x 224 threads, smem-staged M and abundances, coalesced.
// ---------------------------------------------------------------------------
__global__ __launch_bounds__(224) void yhat_kernel2(
    const float* __restrict__ ab, const float* __restrict__ M,
    float* __restrict__ out)
{
    constexpr int CH = NPIX / NCHUNK;  // 128
    __shared__ float sM[PDIM * FDIM];
    __shared__ float sab[CH * PDIM];
    const int t = threadIdx.x;
    const int n0 = blockIdx.x * CH;
    for (int i = t; i < PDIM * FDIM; i += 224) sM[i] = M[i];
    for (int i = t; i < CH * PDIM; i += 224) sab[i] = ab[(long)n0 * PDIM + i];
    __syncthreads();

    for (int i = 0; i < CH; i++) {
        float acc = 0.f;
#pragma unroll
        for (int p = 0; p < PDIM; p++) acc += sab[i * PDIM + p] * sM[p * FDIM + t];
        out[(long)(n0 + i) * FDIM + t] = acc;
    }
}

// ---------------------------------------------------------------------------
extern "C" void kernel_launch(void* const* d_in, const int* in_sizes, int n_in,
                              void* d_out, int out_size)
{
    const float* ab = (const float*)d_in[0];
    const float* Y  = (const float*)d_in[1];
    const float* W1 = (const float*)d_in[2];
    const float* b1 = (const float*)d_in[3];
    const float* W2 = (const float*)d_in[4];
    const float* b2 = (const float*)d_in[5];
    const float* W3 = (const float*)d_in[6];
    const float* b3 = (const float*)d_in[7];
    float* out = (float*)d_out;

    __half *yh, *yl, *h1h, *h1l, *h2h, *h2l;
    __half *w1h, *w1l, *w2h, *w2l, *w3h, *w3l;
    float *lg, *M;
    int* cls;
    cudaGetSymbolAddress((void**)&yh,  g_Yh);
    cudaGetSymbolAddress((void**)&yl,  g_Yl);
    cudaGetSymbolAddress((void**)&h1h, g_h1h);
    cudaGetSymbolAddress((void**)&h1l, g_h1l);
    cudaGetSymbolAddress((void**)&h2h, g_h2h);
    cudaGetSymbolAddress((void**)&h2l, g_h2l);
    cudaGetSymbolAddress((void**)&w1h, g_W1Th);
    cudaGetSymbolAddress((void**)&w1l, g_W1Tl);
    cudaGetSymbolAddress((void**)&w2h, g_W2Th);
    cudaGetSymbolAddress((void**)&w2l, g_W2Tl);
    cudaGetSymbolAddress((void**)&w3h, g_W3Th);
    cudaGetSymbolAddress((void**)&w3l, g_W3Tl);
    cudaGetSymbolAddress((void**)&lg,  g_logits);
    cudaGetSymbolAddress((void**)&cls, g_cls);
    cudaGetSymbolAddress((void**)&M,   g_M);

    constexpr int SMEM = 2 * 30720;  // 61440 bytes (2 stages)
    cudaFuncSetAttribute(mma_gemm_f16<HDIM, FDIM, true, true>,
                         cudaFuncAttributeMaxDynamicSharedMemorySize, SMEM);
    cudaFuncSetAttribute(mma_gemm_f16<HDIM, HDIM, true, true>,
                         cudaFuncAttributeMaxDynamicSharedMemorySize, SMEM);
    cudaFuncSetAttribute(mma_gemm_f16<FDIM, HDIM, false, false>,
                         cudaFuncAttributeMaxDynamicSharedMemorySize, SMEM);

    // prep
    split_kernel<<<(NPIX * FDIM / 4 + 255) / 256, 256>>>(Y, yh, yl, NPIX * FDIM / 4);
    transpose_split_all<<<dim3(8, 8, 3), dim3(32, 8)>>>(
        W1, w1h, w1l, W2, w2h, w2l, W3, w3h, w3l);
    cls_kernel2<<<(NPIX / 2 + 255) / 256, 256>>>(ab, cls);

    // GEMM chain (col blocks of 64)
    mma_gemm_f16<HDIM, FDIM, true, true><<<dim3(HDIM / 64, NPIX / 128), 256, SMEM>>>(
        yh, yl, w1h, w1l, b1, nullptr, h1h, h1l);
    mma_gemm_f16<HDIM, HDIM, true, true><<<dim3(HDIM / 64, NPIX / 128), 256, SMEM>>>(
        h1h, h1l, w2h, w2l, b2, nullptr, h2h, h2l);
    mma_gemm_f16<FDIM, HDIM, false, false><<<dim3((FDIM + 63) / 64, NPIX / 128), 256, SMEM>>>(
        h2h, h2l, w3h, w3l, b3, lg, nullptr, nullptr);

    // masked per-class softmax endmembers
    endmember_part2<<<NCHUNK, 224>>>(lg, Y, cls);
    endmember_combine2<<<PDIM, 224>>>(M);

    // reconstruction
    yhat_kernel2<<<NCHUNK, 224>>>(ab, M, out);
}

// round 9
// speedup vs baseline: 1.0712x; 1.0712x over previous
#include <cuda_runtime.h>
#include <cuda_fp16.h>
#include <cstdint>
#include <float.h>

#define NPIX 65536
#define FDIM 224
#define PDIM 6
#define HDIM 256
#define NCHUNK 512          // pixel chunks for endmember/yhat (128 px each)

// ------------------------- static device scratch ---------------------------
__device__ __half g_Yh[NPIX * FDIM];
__device__ __half g_Yl[NPIX * FDIM];
__device__ __half g_h1h[NPIX * HDIM];
__device__ __half g_h1l[NPIX * HDIM];
__device__ __half g_h2h[NPIX * HDIM];
__device__ __half g_h2l[NPIX * HDIM];
__device__ float  g_logits[NPIX * FDIM];
__device__ int    g_cls[NPIX];
__device__ float  g_M[PDIM * FDIM];
__device__ __half g_W1Th[HDIM * FDIM];
__device__ __half g_W1Tl[HDIM * FDIM];
__device__ __half g_W2Th[HDIM * HDIM];
__device__ __half g_W2Tl[HDIM * HDIM];
__device__ __half g_W3Th[FDIM * HDIM];
__device__ __half g_W3Tl[FDIM * HDIM];
__device__ float  g_part[NCHUNK * PDIM * 3 * FDIM];

// ------------------------------ PTX helpers --------------------------------
__device__ __forceinline__ uint32_t smem_u32(const void* p) {
    uint32_t a;
    asm("{ .reg .u64 t; cvta.to.shared.u64 t, %1; cvt.u32.u64 %0, t; }"
        : "=r"(a) : "l"(p));
    return a;
}
__device__ __forceinline__ void cpa16(uint32_t dst, const void* src, uint32_t sz) {
    asm volatile("cp.async.cg.shared.global [%0], [%1], 16, %2;"
                 :: "r"(dst), "l"(src), "r"(sz) : "memory");
}
__device__ __forceinline__ void cpa_commit() {
    asm volatile("cp.async.commit_group;" ::: "memory");
}
template <int n> __device__ __forceinline__ void cpa_wait() {
    asm volatile("cp.async.wait_group %0;" :: "n"(n) : "memory");
}
__device__ __forceinline__ void ldsm4(uint32_t* r, uint32_t addr) {
    asm volatile("ldmatrix.sync.aligned.m8n8.x4.shared.b16 {%0,%1,%2,%3}, [%4];"
                 : "=r"(r[0]), "=r"(r[1]), "=r"(r[2]), "=r"(r[3]) : "r"(addr));
}
__device__ __forceinline__ void mma_f16(float* d, const uint32_t* a, const uint32_t* b) {
    asm volatile(
        "mma.sync.aligned.m16n8k16.row.col.f32.f16.f16.f32 "
        "{%0,%1,%2,%3}, {%4,%5,%6,%7}, {%8,%9}, {%0,%1,%2,%3};"
        : "+f"(d[0]), "+f"(d[1]), "+f"(d[2]), "+f"(d[3])
        : "r"(a[0]), "r"(a[1]), "r"(a[2]), "r"(a[3]), "r"(b[0]), "r"(b[1]));
}
__device__ __forceinline__ void split_h(float v, __half& hi, __half& lo) {
    hi = __float2half_rn(v);
    lo = __float2half_rn(v - __half2float(hi));
}

// ---------------------------------------------------------------------------
// fp16x3 mma.sync GEMM: C = act(A @ BT^T + bias), fp32-accurate.
// Operands pre-split: A = Ah + Al, BT = Bh + Bl (all __half, K-contiguous).
// Block 128x128, 8 warps (2x4), warp tile 64x32, K chunks of 32.
// 2-stage cp.async, ONE __syncthreads per chunk (prefetch issued after the
// barrier, so the barrier itself is the buffer-reuse fence).
// ---------------------------------------------------------------------------
template <int N, int K, bool RELU, bool SPLIT_OUT>
__global__ __launch_bounds__(256, 2) void mma_gemm_f16(
    const __half* __restrict__ Ah, const __half* __restrict__ Al,
    const __half* __restrict__ Bh, const __half* __restrict__ Bl,
    const float* __restrict__ bias,
    float* __restrict__ Cf, __half* __restrict__ Ch, __half* __restrict__ Cl)
{
    constexpr int NC = K / 32;
    constexpr int ROWB = 80;               // bytes/row: 64B data + 16B pad
    constexpr int COMPB = 128 * ROWB;      // 10240 per component tile
    constexpr int STAGEB = 4 * COMPB;      // 40960: [Ah][Al][Bh][Bl]

    extern __shared__ char sh[];
    const uint32_t sb = smem_u32(sh);

    const int t = threadIdx.x;
    const int lane = t & 31, wid = t >> 5;
    const int wr = wid >> 2;               // 0..1
    const int wc = wid & 3;                // 0..3
    const int row0 = blockIdx.y * 128;
    const int col0 = blockIdx.x * 128;

    float acc[4][4][4];
#pragma unroll
    for (int i = 0; i < 4; i++)
#pragma unroll
        for (int j = 0; j < 4; j++)
#pragma unroll
            for (int k = 0; k < 4; k++) acc[i][j][k] = 0.0f;

    // ---- cp.async mapping: thread t -> row cr (0..63) x2 shots, group g ----
    const int cr = t >> 2;
    const int g  = t & 3;
    const uint32_t dOff1 = (uint32_t)(cr * ROWB + g * 16);
    const uint32_t dOff2 = dOff1 + (uint32_t)(64 * ROWB);

    const __half* Ah0 = Ah + (long)(row0 + cr) * K + g * 8;
    const __half* Al0 = Al + (long)(row0 + cr) * K + g * 8;
    int bn1 = col0 + cr, bn2 = col0 + cr + 64;
    const uint32_t bs1 = (bn1 < N) ? 16u : 0u;
    const uint32_t bs2 = (bn2 < N) ? 16u : 0u;
    if (bn1 >= N) bn1 = N - 1;
    if (bn2 >= N) bn2 = N - 1;
    const __half* Bh1 = Bh + (long)bn1 * K + g * 8;
    const __half* Bh2 = Bh + (long)bn2 * K + g * 8;
    const __half* Bl1 = Bl + (long)bn1 * K + g * 8;
    const __half* Bl2 = Bl + (long)bn2 * K + g * 8;

    // ---- ldmatrix lane offsets (bytes within a component tile) ----
    const uint32_t aLm = (uint32_t)((wr * 64 + (lane & 15)) * ROWB + (lane >> 4) * 16);
    const uint32_t bLm = (uint32_t)((wc * 32 + (lane & 7) + ((lane >> 4) << 3)) * ROWB
                                    + ((lane >> 3) & 1) * 16);

    auto load_chunk = [&](int stage, int k0) {
        const uint32_t st = sb + (uint32_t)(stage * STAGEB);
        cpa16(st + dOff1,                 Ah0 + k0,           16u);
        cpa16(st + dOff2,                 Ah0 + k0 + 64L * K, 16u);
        cpa16(st + COMPB + dOff1,         Al0 + k0,           16u);
        cpa16(st + COMPB + dOff2,         Al0 + k0 + 64L * K, 16u);
        cpa16(st + 2 * COMPB + dOff1,     Bh1 + k0,           bs1);
        cpa16(st + 2 * COMPB + dOff2,     Bh2 + k0,           bs2);
        cpa16(st + 3 * COMPB + dOff1,     Bl1 + k0,           bs1);
        cpa16(st + 3 * COMPB + dOff2,     Bl2 + k0,           bs2);
        cpa_commit();
    };

    load_chunk(0, 0);

    for (int c = 0; c < NC; c++) {
        const int buf = c & 1;
        cpa_wait<0>();                     // chunk c resident
        __syncthreads();                   // ALSO fences buf^1 reuse (iter c-1 done)
        if (c + 1 < NC) load_chunk(buf ^ 1, (c + 1) * 32);

        const uint32_t st = sb + (uint32_t)(buf * STAGEB);
        const uint32_t aHB = st + aLm;
        const uint32_t aLB = st + COMPB + aLm;
        const uint32_t bHB = st + 2 * COMPB + bLm;
        const uint32_t bLB = st + 3 * COMPB + bLm;

#pragma unroll
        for (int kk = 0; kk < 2; kk++) {
            uint32_t bh[4][2], bl[4][2];
#pragma unroll
            for (int pr = 0; pr < 2; pr++) {
                const uint32_t o = (uint32_t)(pr * 16 * ROWB + kk * 32);
                uint32_t r4[4];
                ldsm4(r4, bHB + o);
                bh[pr * 2][0] = r4[0]; bh[pr * 2][1] = r4[1];
                bh[pr * 2 + 1][0] = r4[2]; bh[pr * 2 + 1][1] = r4[3];
                ldsm4(r4, bLB + o);
                bl[pr * 2][0] = r4[0]; bl[pr * 2][1] = r4[1];
                bl[pr * 2 + 1][0] = r4[2]; bl[pr * 2 + 1][1] = r4[3];
            }
#pragma unroll
            for (int mt = 0; mt < 4; mt++) {
                const uint32_t o = (uint32_t)(mt * 16 * ROWB + kk * 32);
                uint32_t ah[4], al[4];
                ldsm4(ah, aHB + o);
                ldsm4(al, aLB + o);
#pragma unroll
                for (int nt = 0; nt < 4; nt++) mma_f16(acc[mt][nt], ah, bh[nt]);
#pragma unroll
                for (int nt = 0; nt < 4; nt++) mma_f16(acc[mt][nt], al, bh[nt]);
#pragma unroll
                for (int nt = 0; nt < 4; nt++) mma_f16(acc[mt][nt], ah, bl[nt]);
            }
        }
    }

    // ---- epilogue ----
    const int rbase = row0 + wr * 64 + (lane >> 2);
    const int cbase = col0 + wc * 32 + (lane & 3) * 2;
#pragma unroll
    for (int nt = 0; nt < 4; nt++) {
        const int cc = cbase + nt * 8;
        if (cc < N) {
            const float bx = bias[cc], by = bias[cc + 1];
#pragma unroll
            for (int mt = 0; mt < 4; mt++) {
                const int r = rbase + mt * 16;
                float v[4];
                v[0] = acc[mt][nt][0] + bx; v[1] = acc[mt][nt][1] + by;
                v[2] = acc[mt][nt][2] + bx; v[3] = acc[mt][nt][3] + by;
                if (RELU) {
#pragma unroll
                    for (int q = 0; q < 4; q++) v[q] = fmaxf(v[q], 0.f);
                }
                if (SPLIT_OUT) {
                    __half h0, l0, h1x, l1, h2x, l2, h3, l3;
                    split_h(v[0], h0, l0); split_h(v[1], h1x, l1);
                    split_h(v[2], h2x, l2); split_h(v[3], h3, l3);
                    *(__half2*)&Ch[(long)r * N + cc]       = __halves2half2(h0, h1x);
                    *(__half2*)&Cl[(long)r * N + cc]       = __halves2half2(l0, l1);
                    *(__half2*)&Ch[(long)(r + 8) * N + cc] = __halves2half2(h2x, h3);
                    *(__half2*)&Cl[(long)(r + 8) * N + cc] = __halves2half2(l2, l3);
                } else {
                    *(float2*)&Cf[(long)r * N + cc]       = make_float2(v[0], v[1]);
                    *(float2*)&Cf[(long)(r + 8) * N + cc] = make_float2(v[2], v[3]);
                }
            }
        }
    }
}

// ---------------------------------------------------------------------------
// Split fp32 array -> (hi, lo) fp16 arrays. n multiple of 4.
// ---------------------------------------------------------------------------
__global__ __launch_bounds__(256) void split_kernel(
    const float* __restrict__ in, __half* __restrict__ hi, __half* __restrict__ lo,
    int n4)
{
    int i = blockIdx.x * 256 + threadIdx.x;
    if (i >= n4) return;
    float4 v = ((const float4*)in)[i];
    __half h0, l0, h1, l1, h2, l2, h3, l3;
    split_h(v.x, h0, l0); split_h(v.y, h1, l1);
    split_h(v.z, h2, l2); split_h(v.w, h3, l3);
    ((__half2*)hi)[i * 2]     = __halves2half2(h0, h1);
    ((__half2*)hi)[i * 2 + 1] = __halves2half2(h2, h3);
    ((__half2*)lo)[i * 2]     = __halves2half2(l0, l1);
    ((__half2*)lo)[i * 2 + 1] = __halves2half2(l2, l3);
}

// ---------------------------------------------------------------------------
// Fused transpose+split for all 3 weight matrices. grid (8,8,3), block (32,8).
// ---------------------------------------------------------------------------
__global__ void transpose_split_all(
    const float* __restrict__ W1, __half* __restrict__ T1h, __half* __restrict__ T1l,
    const float* __restrict__ W2, __half* __restrict__ T2h, __half* __restrict__ T2l,
    const float* __restrict__ W3, __half* __restrict__ T3h, __half* __restrict__ T3l)
{
    const float* W; __half* Th; __half* Tl; int R, C;
    if (blockIdx.z == 0)      { W = W1; Th = T1h; Tl = T1l; R = FDIM; C = HDIM; }
    else if (blockIdx.z == 1) { W = W2; Th = T2h; Tl = T2l; R = HDIM; C = HDIM; }
    else                      { W = W3; Th = T3h; Tl = T3l; R = HDIM; C = FDIM; }
    if ((int)blockIdx.x * 32 >= C || (int)blockIdx.y * 32 >= R) return;

    __shared__ float tb[32][33];
    int c = blockIdx.x * 32 + threadIdx.x;
    int r0 = blockIdx.y * 32;
    for (int j = threadIdx.y; j < 32; j += 8)
        tb[j][threadIdx.x] = W[(r0 + j) * C + c];
    __syncthreads();
    int rOut = r0 + threadIdx.x;
    int cBase = blockIdx.x * 32;
    for (int j = threadIdx.y; j < 32; j += 8) {
        float v = tb[threadIdx.x][j];
        __half h, l;
        split_h(v, h, l);
        Th[(long)(cBase + j) * R + rOut] = h;
        Tl[(long)(cBase + j) * R + rOut] = l;
    }
}

// ---------------------------------------------------------------------------
// argmax over P=6 per pixel, pixel-pair vectorized (12 floats = 3 float4).
// ---------------------------------------------------------------------------
__global__ __launch_bounds__(256) void cls_kernel2(
    const float* __restrict__ ab, int* __restrict__ cls)
{
    int i = blockIdx.x * 256 + threadIdx.x;   // pair index
    if (i >= NPIX / 2) return;
    const float4* p = (const float4*)(ab + (long)i * 12);
    float4 v0 = p[0], v1 = p[1], v2 = p[2];
    float a[6] = { v0.x, v0.y, v0.z, v0.w, v1.x, v1.y };
    float b[6] = { v1.z, v1.w, v2.x, v2.y, v2.z, v2.w };
    int ba = 0, bb = 0;
    float ma = a[0], mb = b[0];
#pragma unroll
    for (int q = 1; q < 6; q++) {
        if (a[q] > ma) { ma = a[q]; ba = q; }
        if (b[q] > mb) { mb = b[q]; bb = q; }
    }
    cls[i * 2] = ba;
    cls[i * 2 + 1] = bb;
}

// ---------------------------------------------------------------------------
// Endmember partials: thread <-> feature mapping, fully coalesced rows.
// grid NCHUNK blocks x 224 threads; each block: 128 consecutive pixels.
// ---------------------------------------------------------------------------
__global__ __launch_bounds__(224) void endmember_part2(
    const float* __restrict__ logits, const float* __restrict__ Y,
    const int* __restrict__ cls)
{
    const int blk = blockIdx.x;
    const int t = threadIdx.x;              // feature
    const int n0 = blk * (NPIX / NCHUNK);   // 128 pixels per chunk

    __shared__ int scls[NPIX / NCHUNK];
    for (int i = t; i < NPIX / NCHUNK; i += 224) scls[i] = cls[n0 + i];
    __syncthreads();

    float m[PDIM], s[PDIM], sy[PDIM];
#pragma unroll
    for (int p = 0; p < PDIM; p++) { m[p] = -FLT_MAX; s[p] = 0.f; sy[p] = 0.f; }

    for (int i = 0; i < NPIX / NCHUNK; i++) {
        const int c = scls[i];
        const long off = (long)(n0 + i) * FDIM + t;
        const float l = logits[off];
        const float y = Y[off];
        float mc = m[0], sc = s[0], syc = sy[0];
#pragma unroll
        for (int p = 1; p < PDIM; p++) {
            bool e = (c == p);
            mc = e ? m[p] : mc; sc = e ? s[p] : sc; syc = e ? sy[p] : syc;
        }
        float mn  = fmaxf(mc, l);
        float sca = __expf(mc - mn);
        float ea  = __expf(l - mn);
        float sn  = sc * sca + ea;
        float syn = syc * sca + ea * y;
#pragma unroll
        for (int p = 0; p < PDIM; p++) {
            bool e = (c == p);
            m[p] = e ? mn : m[p]; s[p] = e ? sn : s[p]; sy[p] = e ? syn : sy[p];
        }
    }

#pragma unroll
    for (int p = 0; p < PDIM; p++) {
        long base = (((long)blk * PDIM + p) * 3) * FDIM + t;
        g_part[base]             = m[p];
        g_part[base + FDIM]      = s[p];
        g_part[base + 2 * FDIM]  = sy[p];
    }
}

// grid PDIM blocks x 224 threads
__global__ __launch_bounds__(224) void endmember_combine2(float* __restrict__ Mo) {
    const int p = blockIdx.x;
    const int f = threadIdx.x;
    float m = -FLT_MAX, s = 0.f, sy = 0.f;
    for (int b = 0; b < NCHUNK; b++) {
        long base = (((long)b * PDIM + p) * 3) * FDIM + f;
        float m2 = g_part[base];
        float s2 = g_part[base + FDIM];
        float sy2 = g_part[base + 2 * FDIM];
        float mx = fmaxf(m, m2);
        float e1 = __expf(m - mx), e2 = __expf(m2 - mx);
        s  = s * e1 + s2 * e2;
        sy = sy * e1 + sy2 * e2;
        m = mx;
    }
    Mo[p * FDIM + f] = (s > 0.f) ? (sy / s) : 0.0f;
}

// ---------------------------------------------------------------------------
// Y_hat: grid NCHUNK x 224 threads, smem-staged M and abundances, coalesced.
// ---------------------------------------------------------------------------
__global__ __launch_bounds__(224) void yhat_kernel2(
    const float* __restrict__ ab, const float* __restrict__ M,
    float* __restrict__ out)
{
    constexpr int CH = NPIX / NCHUNK;  // 128
    __shared__ float sM[PDIM * FDIM];
    __shared__ float sab[CH * PDIM];
    const int t = threadIdx.x;
    const int n0 = blockIdx.x * CH;
    for (int i = t; i < PDIM * FDIM; i += 224) sM[i] = M[i];
    for (int i = t; i < CH * PDIM; i += 224) sab[i] = ab[(long)n0 * PDIM + i];
    __syncthreads();

    for (int i = 0; i < CH; i++) {
        float acc = 0.f;
#pragma unroll
        for (int p = 0; p < PDIM; p++) acc += sab[i * PDIM + p] * sM[p * FDIM + t];
        out[(long)(n0 + i) * FDIM + t] = acc;
    }
}

// ---------------------------------------------------------------------------
extern "C" void kernel_launch(void* const* d_in, const int* in_sizes, int n_in,
                              void* d_out, int out_size)
{
    const float* ab = (const float*)d_in[0];
    const float* Y  = (const float*)d_in[1];
    const float* W1 = (const float*)d_in[2];
    const float* b1 = (const float*)d_in[3];
    const float* W2 = (const float*)d_in[4];
    const float* b2 = (const float*)d_in[5];
    const float* W3 = (const float*)d_in[6];
    const float* b3 = (const float*)d_in[7];
    float* out = (float*)d_out;

    __half *yh, *yl, *h1h, *h1l, *h2h, *h2l;
    __half *w1h, *w1l, *w2h, *w2l, *w3h, *w3l;
    float *lg, *M;
    int* cls;
    cudaGetSymbolAddress((void**)&yh,  g_Yh);
    cudaGetSymbolAddress((void**)&yl,  g_Yl);
    cudaGetSymbolAddress((void**)&h1h, g_h1h);
    cudaGetSymbolAddress((void**)&h1l, g_h1l);
    cudaGetSymbolAddress((void**)&h2h, g_h2h);
    cudaGetSymbolAddress((void**)&h2l, g_h2l);
    cudaGetSymbolAddress((void**)&w1h, g_W1Th);
    cudaGetSymbolAddress((void**)&w1l, g_W1Tl);
    cudaGetSymbolAddress((void**)&w2h, g_W2Th);
    cudaGetSymbolAddress((void**)&w2l, g_W2Tl);
    cudaGetSymbolAddress((void**)&w3h, g_W3Th);
    cudaGetSymbolAddress((void**)&w3l, g_W3Tl);
    cudaGetSymbolAddress((void**)&lg,  g_logits);
    cudaGetSymbolAddress((void**)&cls, g_cls);
    cudaGetSymbolAddress((void**)&M,   g_M);

    constexpr int SMEM = 2 * 4 * 128 * 80;  // 81920 bytes (2 stages)
    cudaFuncSetAttribute(mma_gemm_f16<HDIM, FDIM, true, true>,
                         cudaFuncAttributeMaxDynamicSharedMemorySize, SMEM);
    cudaFuncSetAttribute(mma_gemm_f16<HDIM, HDIM, true, true>,
                         cudaFuncAttributeMaxDynamicSharedMemorySize, SMEM);
    cudaFuncSetAttribute(mma_gemm_f16<FDIM, HDIM, false, false>,
                         cudaFuncAttributeMaxDynamicSharedMemorySize, SMEM);

    // prep
    split_kernel<<<(NPIX * FDIM / 4 + 255) / 256, 256>>>(Y, yh, yl, NPIX * FDIM / 4);
    transpose_split_all<<<dim3(8, 8, 3), dim3(32, 8)>>>(
        W1, w1h, w1l, W2, w2h, w2l, W3, w3h, w3l);
    cls_kernel2<<<(NPIX / 2 + 255) / 256, 256>>>(ab, cls);

    // GEMM chain (128x128 tiles)
    mma_gemm_f16<HDIM, FDIM, true, true><<<dim3(2, NPIX / 128), 256, SMEM>>>(
        yh, yl, w1h, w1l, b1, nullptr, h1h, h1l);
    mma_gemm_f16<HDIM, HDIM, true, true><<<dim3(2, NPIX / 128), 256, SMEM>>>(
        h1h, h1l, w2h, w2l, b2, nullptr, h2h, h2l);
    mma_gemm_f16<FDIM, HDIM, false, false><<<dim3(2, NPIX / 128), 256, SMEM>>>(
        h2h, h2l, w3h, w3l, b3, lg, nullptr, nullptr);

    // masked per-class softmax endmembers
    endmember_part2<<<NCHUNK, 224>>>(lg, Y, cls);
    endmember_combine2<<<PDIM, 224>>>(M);

    // reconstruction
    yhat_kernel2<<<NCHUNK, 224>>>(ab, M, out);
}

// round 10
// speedup vs baseline: 1.0758x; 1.0043x over previous
#include <cuda_runtime.h>
#include <cuda_fp16.h>
#include <cstdint>
#include <float.h>

#define NPIX 65536
#define FDIM 224
#define PDIM 6
#define HDIM 256
#define NCHUNK 512          // pixel chunks for endmember/yhat (128 px each)

// ------------------------- static device scratch ---------------------------
__device__ __half g_Yh[NPIX * FDIM];
__device__ __half g_Yl[NPIX * FDIM];
__device__ __half g_h1h[NPIX * HDIM];
__device__ __half g_h1l[NPIX * HDIM];
__device__ __half g_h2h[NPIX * HDIM];
__device__ __half g_h2l[NPIX * HDIM];
__device__ float  g_logits[NPIX * FDIM];
__device__ int    g_cls[NPIX];
__device__ float  g_M[PDIM * FDIM];
__device__ __half g_W1Th[HDIM * FDIM];
__device__ __half g_W1Tl[HDIM * FDIM];
__device__ __half g_W2Th[HDIM * HDIM];
__device__ __half g_W2Tl[HDIM * HDIM];
__device__ __half g_W3Th[FDIM * HDIM];
__device__ __half g_W3Tl[FDIM * HDIM];
__device__ float  g_part[NCHUNK * PDIM * 3 * FDIM];

// ------------------------------ PTX helpers --------------------------------
__device__ __forceinline__ uint32_t smem_u32(const void* p) {
    uint32_t a;
    asm("{ .reg .u64 t; cvta.to.shared.u64 t, %1; cvt.u32.u64 %0, t; }"
        : "=r"(a) : "l"(p));
    return a;
}
__device__ __forceinline__ void cpa16(uint32_t dst, const void* src, uint32_t sz) {
    asm volatile("cp.async.cg.shared.global [%0], [%1], 16, %2;"
                 :: "r"(dst), "l"(src), "r"(sz) : "memory");
}
__device__ __forceinline__ void cpa_commit() {
    asm volatile("cp.async.commit_group;" ::: "memory");
}
template <int n> __device__ __forceinline__ void cpa_wait() {
    asm volatile("cp.async.wait_group %0;" :: "n"(n) : "memory");
}
__device__ __forceinline__ void ldsm4(uint32_t* r, uint32_t addr) {
    asm volatile("ldmatrix.sync.aligned.m8n8.x4.shared.b16 {%0,%1,%2,%3}, [%4];"
                 : "=r"(r[0]), "=r"(r[1]), "=r"(r[2]), "=r"(r[3]) : "r"(addr));
}
__device__ __forceinline__ void mma_f16(float* d, const uint32_t* a, const uint32_t* b) {
    asm volatile(
        "mma.sync.aligned.m16n8k16.row.col.f32.f16.f16.f32 "
        "{%0,%1,%2,%3}, {%4,%5,%6,%7}, {%8,%9}, {%0,%1,%2,%3};"
        : "+f"(d[0]), "+f"(d[1]), "+f"(d[2]), "+f"(d[3])
        : "r"(a[0]), "r"(a[1]), "r"(a[2]), "r"(a[3]), "r"(b[0]), "r"(b[1]));
}
__device__ __forceinline__ void split_h(float v, __half& hi, __half& lo) {
    hi = __float2half_rn(v);
    lo = __float2half_rn(v - __half2float(hi));
}

// ---------------------------------------------------------------------------
// fp16x3 mma.sync GEMM: C = act(A @ BT^T + bias), fp32-accurate.
// Operands pre-split: A = Ah + Al, BT = Bh + Bl (all __half, K-contiguous).
// Block 128x128, 8 warps (2x4), warp tile 64x32, K chunks of 32.
// 2-stage cp.async, ONE __syncthreads per chunk. Inner loop processes m-tiles
// in PAIRS so same-accumulator HMMA reuse distance is 8 (covers HMMA latency).
// ---------------------------------------------------------------------------
template <int N, int K, bool RELU, bool SPLIT_OUT>
__global__ __launch_bounds__(256, 2) void mma_gemm_f16(
    const __half* __restrict__ Ah, const __half* __restrict__ Al,
    const __half* __restrict__ Bh, const __half* __restrict__ Bl,
    const float* __restrict__ bias,
    float* __restrict__ Cf, __half* __restrict__ Ch, __half* __restrict__ Cl)
{
    constexpr int NC = K / 32;
    constexpr int ROWB = 80;               // bytes/row: 64B data + 16B pad
    constexpr int COMPB = 128 * ROWB;      // 10240 per component tile
    constexpr int STAGEB = 4 * COMPB;      // 40960: [Ah][Al][Bh][Bl]

    extern __shared__ char sh[];
    const uint32_t sb = smem_u32(sh);

    const int t = threadIdx.x;
    const int lane = t & 31, wid = t >> 5;
    const int wr = wid >> 2;               // 0..1
    const int wc = wid & 3;                // 0..3
    const int row0 = blockIdx.y * 128;
    const int col0 = blockIdx.x * 128;

    float acc[4][4][4];
#pragma unroll
    for (int i = 0; i < 4; i++)
#pragma unroll
        for (int j = 0; j < 4; j++)
#pragma unroll
            for (int k = 0; k < 4; k++) acc[i][j][k] = 0.0f;

    // ---- cp.async mapping: thread t -> row cr (0..63) x2 shots, group g ----
    const int cr = t >> 2;
    const int g  = t & 3;
    const uint32_t dOff1 = (uint32_t)(cr * ROWB + g * 16);
    const uint32_t dOff2 = dOff1 + (uint32_t)(64 * ROWB);

    const __half* Ah0 = Ah + (long)(row0 + cr) * K + g * 8;
    const __half* Al0 = Al + (long)(row0 + cr) * K + g * 8;
    int bn1 = col0 + cr, bn2 = col0 + cr + 64;
    const uint32_t bs1 = (bn1 < N) ? 16u : 0u;
    const uint32_t bs2 = (bn2 < N) ? 16u : 0u;
    if (bn1 >= N) bn1 = N - 1;
    if (bn2 >= N) bn2 = N - 1;
    const __half* Bh1 = Bh + (long)bn1 * K + g * 8;
    const __half* Bh2 = Bh + (long)bn2 * K + g * 8;
    const __half* Bl1 = Bl + (long)bn1 * K + g * 8;
    const __half* Bl2 = Bl + (long)bn2 * K + g * 8;

    // ---- ldmatrix lane offsets (bytes within a component tile) ----
    const uint32_t aLm = (uint32_t)((wr * 64 + (lane & 15)) * ROWB + (lane >> 4) * 16);
    const uint32_t bLm = (uint32_t)((wc * 32 + (lane & 7) + ((lane >> 4) << 3)) * ROWB
                                    + ((lane >> 3) & 1) * 16);

    auto load_chunk = [&](int stage, int k0) {
        const uint32_t st = sb + (uint32_t)(stage * STAGEB);
        cpa16(st + dOff1,                 Ah0 + k0,           16u);
        cpa16(st + dOff2,                 Ah0 + k0 + 64L * K, 16u);
        cpa16(st + COMPB + dOff1,         Al0 + k0,           16u);
        cpa16(st + COMPB + dOff2,         Al0 + k0 + 64L * K, 16u);
        cpa16(st + 2 * COMPB + dOff1,     Bh1 + k0,           bs1);
        cpa16(st + 2 * COMPB + dOff2,     Bh2 + k0,           bs2);
        cpa16(st + 3 * COMPB + dOff1,     Bl1 + k0,           bs1);
        cpa16(st + 3 * COMPB + dOff2,     Bl2 + k0,           bs2);
        cpa_commit();
    };

    load_chunk(0, 0);

    for (int c = 0; c < NC; c++) {
        const int buf = c & 1;
        cpa_wait<0>();                     // chunk c resident
        __syncthreads();                   // ALSO fences buf^1 reuse (iter c-1 done)
        if (c + 1 < NC) load_chunk(buf ^ 1, (c + 1) * 32);

        const uint32_t st = sb + (uint32_t)(buf * STAGEB);
        const uint32_t aHB = st + aLm;
        const uint32_t aLB = st + COMPB + aLm;
        const uint32_t bHB = st + 2 * COMPB + bLm;
        const uint32_t bLB = st + 3 * COMPB + bLm;

#pragma unroll
        for (int kk = 0; kk < 2; kk++) {
            uint32_t bh[4][2], bl[4][2];
#pragma unroll
            for (int pr = 0; pr < 2; pr++) {
                const uint32_t o = (uint32_t)(pr * 16 * ROWB + kk * 32);
                uint32_t r4[4];
                ldsm4(r4, bHB + o);
                bh[pr * 2][0] = r4[0]; bh[pr * 2][1] = r4[1];
                bh[pr * 2 + 1][0] = r4[2]; bh[pr * 2 + 1][1] = r4[3];
                ldsm4(r4, bLB + o);
                bl[pr * 2][0] = r4[0]; bl[pr * 2][1] = r4[1];
                bl[pr * 2 + 1][0] = r4[2]; bl[pr * 2 + 1][1] = r4[3];
            }
            // m-tiles in pairs: same-acc reuse distance 8 MMAs, per-acc term
            // order (hh -> lh -> hl) unchanged => identical numerics.
#pragma unroll
            for (int mp = 0; mp < 2; mp++) {
                const int m0 = mp * 2, m1 = mp * 2 + 1;
                const uint32_t o0 = (uint32_t)(m0 * 16 * ROWB + kk * 32);
                const uint32_t o1 = (uint32_t)(m1 * 16 * ROWB + kk * 32);
                uint32_t ah0[4], al0[4], ah1[4], al1[4];
                ldsm4(ah0, aHB + o0);
                ldsm4(al0, aLB + o0);
                ldsm4(ah1, aHB + o1);
                ldsm4(al1, aLB + o1);
#pragma unroll
                for (int nt = 0; nt < 4; nt++) mma_f16(acc[m0][nt], ah0, bh[nt]);
#pragma unroll
                for (int nt = 0; nt < 4; nt++) mma_f16(acc[m1][nt], ah1, bh[nt]);
#pragma unroll
                for (int nt = 0; nt < 4; nt++) mma_f16(acc[m0][nt], al0, bh[nt]);
#pragma unroll
                for (int nt = 0; nt < 4; nt++) mma_f16(acc[m1][nt], al1, bh[nt]);
#pragma unroll
                for (int nt = 0; nt < 4; nt++) mma_f16(acc[m0][nt], ah0, bl[nt]);
#pragma unroll
                for (int nt = 0; nt < 4; nt++) mma_f16(acc[m1][nt], ah1, bl[nt]);
            }
        }
    }

    // ---- epilogue ----
    const int rbase = row0 + wr * 64 + (lane >> 2);
    const int cbase = col0 + wc * 32 + (lane & 3) * 2;
#pragma unroll
    for (int nt = 0; nt < 4; nt++) {
        const int cc = cbase + nt * 8;
        if (cc < N) {
            const float bx = bias[cc], by = bias[cc + 1];
#pragma unroll
            for (int mt = 0; mt < 4; mt++) {
                const int r = rbase + mt * 16;
                float v[4];
                v[0] = acc[mt][nt][0] + bx; v[1] = acc[mt][nt][1] + by;
                v[2] = acc[mt][nt][2] + bx; v[3] = acc[mt][nt][3] + by;
                if (RELU) {
#pragma unroll
                    for (int q = 0; q < 4; q++) v[q] = fmaxf(v[q], 0.f);
                }
                if (SPLIT_OUT) {
                    __half h0, l0, h1x, l1, h2x, l2, h3, l3;
                    split_h(v[0], h0, l0); split_h(v[1], h1x, l1);
                    split_h(v[2], h2x, l2); split_h(v[3], h3, l3);
                    *(__half2*)&Ch[(long)r * N + cc]       = __halves2half2(h0, h1x);
                    *(__half2*)&Cl[(long)r * N + cc]       = __halves2half2(l0, l1);
                    *(__half2*)&Ch[(long)(r + 8) * N + cc] = __halves2half2(h2x, h3);
                    *(__half2*)&Cl[(long)(r + 8) * N + cc] = __halves2half2(l2, l3);
                } else {
                    *(float2*)&Cf[(long)r * N + cc]       = make_float2(v[0], v[1]);
                    *(float2*)&Cf[(long)(r + 8) * N + cc] = make_float2(v[2], v[3]);
                }
            }
        }
    }
}

// ---------------------------------------------------------------------------
// Split fp32 array -> (hi, lo) fp16 arrays. n multiple of 4.
// ---------------------------------------------------------------------------
__global__ __launch_bounds__(256) void split_kernel(
    const float* __restrict__ in, __half* __restrict__ hi, __half* __restrict__ lo,
    int n4)
{
    int i = blockIdx.x * 256 + threadIdx.x;
    if (i >= n4) return;
    float4 v = ((const float4*)in)[i];
    __half h0, l0, h1, l1, h2, l2, h3, l3;
    split_h(v.x, h0, l0); split_h(v.y, h1, l1);
    split_h(v.z, h2, l2); split_h(v.w, h3, l3);
    ((__half2*)hi)[i * 2]     = __halves2half2(h0, h1);
    ((__half2*)hi)[i * 2 + 1] = __halves2half2(h2, h3);
    ((__half2*)lo)[i * 2]     = __halves2half2(l0, l1);
    ((__half2*)lo)[i * 2 + 1] = __halves2half2(l2, l3);
}

// ---------------------------------------------------------------------------
// Fused transpose+split for all 3 weight matrices. grid (8,8,3), block (32,8).
// ---------------------------------------------------------------------------
__global__ void transpose_split_all(
    const float* __restrict__ W1, __half* __restrict__ T1h, __half* __restrict__ T1l,
    const float* __restrict__ W2, __half* __restrict__ T2h, __half* __restrict__ T2l,
    const float* __restrict__ W3, __half* __restrict__ T3h, __half* __restrict__ T3l)
{
    const float* W; __half* Th; __half* Tl; int R, C;
    if (blockIdx.z == 0)      { W = W1; Th = T1h; Tl = T1l; R = FDIM; C = HDIM; }
    else if (blockIdx.z == 1) { W = W2; Th = T2h; Tl = T2l; R = HDIM; C = HDIM; }
    else                      { W = W3; Th = T3h; Tl = T3l; R = HDIM; C = FDIM; }
    if ((int)blockIdx.x * 32 >= C || (int)blockIdx.y * 32 >= R) return;

    __shared__ float tb[32][33];
    int c = blockIdx.x * 32 + threadIdx.x;
    int r0 = blockIdx.y * 32;
    for (int j = threadIdx.y; j < 32; j += 8)
        tb[j][threadIdx.x] = W[(r0 + j) * C + c];
    __syncthreads();
    int rOut = r0 + threadIdx.x;
    int cBase = blockIdx.x * 32;
    for (int j = threadIdx.y; j < 32; j += 8) {
        float v = tb[threadIdx.x][j];
        __half h, l;
        split_h(v, h, l);
        Th[(long)(cBase + j) * R + rOut] = h;
        Tl[(long)(cBase + j) * R + rOut] = l;
    }
}

// ---------------------------------------------------------------------------
// argmax over P=6 per pixel, pixel-pair vectorized (12 floats = 3 float4).
// ---------------------------------------------------------------------------
__global__ __launch_bounds__(256) void cls_kernel2(
    const float* __restrict__ ab, int* __restrict__ cls)
{
    int i = blockIdx.x * 256 + threadIdx.x;   // pair index
    if (i >= NPIX / 2) return;
    const float4* p = (const float4*)(ab + (long)i * 12);
    float4 v0 = p[0], v1 = p[1], v2 = p[2];
    float a[6] = { v0.x, v0.y, v0.z, v0.w, v1.x, v1.y };
    float b[6] = { v1.z, v1.w, v2.x, v2.y, v2.z, v2.w };
    int ba = 0, bb = 0;
    float ma = a[0], mb = b[0];
#pragma unroll
    for (int q = 1; q < 6; q++) {
        if (a[q] > ma) { ma = a[q]; ba = q; }
        if (b[q] > mb) { mb = b[q]; bb = q; }
    }
    cls[i * 2] = ba;
    cls[i * 2 + 1] = bb;
}

// ---------------------------------------------------------------------------
// Endmember partials: thread <-> feature mapping, fully coalesced rows.
// grid NCHUNK blocks x 224 threads; each block: 128 consecutive pixels.
// ---------------------------------------------------------------------------
__global__ __launch_bounds__(224) void endmember_part2(
    const float* __restrict__ logits, const float* __restrict__ Y,
    const int* __restrict__ cls)
{
    const int blk = blockIdx.x;
    const int t = threadIdx.x;              // feature
    const int n0 = blk * (NPIX / NCHUNK);   // 128 pixels per chunk

    __shared__ int scls[NPIX / NCHUNK];
    for (int i = t; i < NPIX / NCHUNK; i += 224) scls[i] = cls[n0 + i];
    __syncthreads();

    float m[PDIM], s[PDIM], sy[PDIM];
#pragma unroll
    for (int p = 0; p < PDIM; p++) { m[p] = -FLT_MAX; s[p] = 0.f; sy[p] = 0.f; }

    for (int i = 0; i < NPIX / NCHUNK; i++) {
        const int c = scls[i];
        const long off = (long)(n0 + i) * FDIM + t;
        const float l = logits[off];
        const float y = Y[off];
        float mc = m[0], sc = s[0], syc = sy[0];
#pragma unroll
        for (int p = 1; p < PDIM; p++) {
            bool e = (c == p);
            mc = e ? m[p] : mc; sc = e ? s[p] : sc; syc = e ? sy[p] : syc;
        }
        float mn  = fmaxf(mc, l);
        float sca = __expf(mc - mn);
        float ea  = __expf(l - mn);
        float sn  = sc * sca + ea;
        float syn = syc * sca + ea * y;
#pragma unroll
        for (int p = 0; p < PDIM; p++) {
            bool e = (c == p);
            m[p] = e ? mn : m[p]; s[p] = e ? sn : s[p]; sy[p] = e ? syn : sy[p];
        }
    }

#pragma unroll
    for (int p = 0; p < PDIM; p++) {
        long base = (((long)blk * PDIM + p) * 3) * FDIM + t;
        g_part[base]             = m[p];
        g_part[base + FDIM]      = s[p];
        g_part[base + 2 * FDIM]  = sy[p];
    }
}

// grid PDIM blocks x 224 threads
__global__ __launch_bounds__(224) void endmember_combine2(float* __restrict__ Mo) {
    const int p = blockIdx.x;
    const int f = threadIdx.x;
    float m = -FLT_MAX, s = 0.f, sy = 0.f;
    for (int b = 0; b < NCHUNK; b++) {
        long base = (((long)b * PDIM + p) * 3) * FDIM + f;
        float m2 = g_part[base];
        float s2 = g_part[base + FDIM];
        float sy2 = g_part[base + 2 * FDIM];
        float mx = fmaxf(m, m2);
        float e1 = __expf(m - mx), e2 = __expf(m2 - mx);
        s  = s * e1 + s2 * e2;
        sy = sy * e1 + sy2 * e2;
        m = mx;
    }
    Mo[p * FDIM + f] = (s > 0.f) ? (sy / s) : 0.0f;
}

// ---------------------------------------------------------------------------
// Y_hat: grid NCHUNK x 224 threads, smem-staged M and abundances, coalesced.
// ---------------------------------------------------------------------------
__global__ __launch_bounds__(224) void yhat_kernel2(
    const float* __restrict__ ab, const float* __restrict__ M,
    float* __restrict__ out)
{
    constexpr int CH = NPIX / NCHUNK;  // 128
    __shared__ float sM[PDIM * FDIM];
    __shared__ float sab[CH * PDIM];
    const int t = threadIdx.x;
    const int n0 = blockIdx.x * CH;
    for (int i = t; i < PDIM * FDIM; i += 224) sM[i] = M[i];
    for (int i = t; i < CH * PDIM; i += 224) sab[i] = ab[(long)n0 * PDIM + i];
    __syncthreads();

    for (int i = 0; i < CH; i++) {
        float acc = 0.f;
#pragma unroll
        for (int p = 0; p < PDIM; p++) acc += sab[i * PDIM + p] * sM[p * FDIM + t];
        out[(long)(n0 + i) * FDIM + t] = acc;
    }
}

// ---------------------------------------------------------------------------
extern "C" void kernel_launch(void* const* d_in, const int* in_sizes, int n_in,
                              void* d_out, int out_size)
{
    const float* ab = (const float*)d_in[0];
    const float* Y  = (const float*)d_in[1];
    const float* W1 = (const float*)d_in[2];
    const float* b1 = (const float*)d_in[3];
    const float* W2 = (const float*)d_in[4];
    const float* b2 = (const float*)d_in[5];
    const float* W3 = (const float*)d_in[6];
    const float* b3 = (const float*)d_in[7];
    float* out = (float*)d_out;

    __half *yh, *yl, *h1h, *h1l, *h2h, *h2l;
    __half *w1h, *w1l, *w2h, *w2l, *w3h, *w3l;
    float *lg, *M;
    int* cls;
    cudaGetSymbolAddress((void**)&yh,  g_Yh);
    cudaGetSymbolAddress((void**)&yl,  g_Yl);
    cudaGetSymbolAddress((void**)&h1h, g_h1h);
    cudaGetSymbolAddress((void**)&h1l, g_h1l);
    cudaGetSymbolAddress((void**)&h2h, g_h2h);
    cudaGetSymbolAddress((void**)&h2l, g_h2l);
    cudaGetSymbolAddress((void**)&w1h, g_W1Th);
    cudaGetSymbolAddress((void**)&w1l, g_W1Tl);
    cudaGetSymbolAddress((void**)&w2h, g_W2Th);
    cudaGetSymbolAddress((void**)&w2l, g_W2Tl);
    cudaGetSymbolAddress((void**)&w3h, g_W3Th);
    cudaGetSymbolAddress((void**)&w3l, g_W3Tl);
    cudaGetSymbolAddress((void**)&lg,  g_logits);
    cudaGetSymbolAddress((void**)&cls, g_cls);
    cudaGetSymbolAddress((void**)&M,   g_M);

    constexpr int SMEM = 2 * 4 * 128 * 80;  // 81920 bytes (2 stages)
    cudaFuncSetAttribute(mma_gemm_f16<HDIM, FDIM, true, true>,
                         cudaFuncAttributeMaxDynamicSharedMemorySize, SMEM);
    cudaFuncSetAttribute(mma_gemm_f16<HDIM, HDIM, true, true>,
                         cudaFuncAttributeMaxDynamicSharedMemorySize, SMEM);
    cudaFuncSetAttribute(mma_gemm_f16<FDIM, HDIM, false, false>,
                         cudaFuncAttributeMaxDynamicSharedMemorySize, SMEM);

    // prep
    split_kernel<<<(NPIX * FDIM / 4 + 255) / 256, 256>>>(Y, yh, yl, NPIX * FDIM / 4);
    transpose_split_all<<<dim3(8, 8, 3), dim3(32, 8)>>>(
        W1, w1h, w1l, W2, w2h, w2l, W3, w3h, w3l);
    cls_kernel2<<<(NPIX / 2 + 255) / 256, 256>>>(ab, cls);

    // GEMM chain (128x128 tiles)
    mma_gemm_f16<HDIM, FDIM, true, true><<<dim3(2, NPIX / 128), 256, SMEM>>>(
        yh, yl, w1h, w1l, b1, nullptr, h1h, h1l);
    mma_gemm_f16<HDIM, HDIM, true, true><<<dim3(2, NPIX / 128), 256, SMEM>>>(
        h1h, h1l, w2h, w2l, b2, nullptr, h2h, h2l);
    mma_gemm_f16<FDIM, HDIM, false, false><<<dim3(2, NPIX / 128), 256, SMEM>>>(
        h2h, h2l, w3h, w3l, b3, lg, nullptr, nullptr);

    // masked per-class softmax endmembers
    endmember_part2<<<NCHUNK, 224>>>(lg, Y, cls);
    endmember_combine2<<<PDIM, 224>>>(M);

    // reconstruction
    yhat_kernel2<<<NCHUNK, 224>>>(ab, M, out);
}